// round 1
// baseline (speedup 1.0000x reference)
#include <cuda_runtime.h>

#define C_IN   512
#define K_OUT  512
#define IH     38
#define IW     50
#define HWPIX  1900
#define NANCH  17100
#define NSORT  32768
#define PRE_N  6000
#define POST_N 300
#define MASKW  94        // ceil(6000/64)

// ---------------- device scratch (static, no allocation) ----------------
__device__ float g_h1T[HWPIX * K_OUT];                 // conv output, [pixel][k]
__device__ float g_box[NANCH * 4];                     // decoded clipped boxes
__device__ unsigned long long g_keys[NSORT];           // (score<<32)|~idx
__device__ float g_tb[PRE_N * 4];                      // top-6000 boxes (sorted)
__device__ unsigned long long g_mask[(size_t)PRE_N * MASKW];

__constant__ float c_ab[9][4] = {
  {-37.254833f,  -82.50967f,   53.254833f,  98.50967f},
  {-82.50967f,  -173.01933f,   98.50967f,  189.01933f},
  {-173.01933f, -354.03867f,  189.01933f,  370.03867f},
  {-56.0f,       -56.0f,        72.0f,       72.0f},
  {-120.0f,     -120.0f,       136.0f,      136.0f},
  {-248.0f,     -248.0f,       264.0f,      264.0f},
  {-82.50967f,   -37.254833f,  98.50967f,   53.254833f},
  {-173.01933f,  -82.50967f,  189.01933f,   98.50967f},
  {-354.03867f, -173.01933f,  370.03867f,  189.01933f}};

// ---------------- 3x3 conv + bias + relu -> g_h1T[p][k] ----------------
// tile: 64 output channels x (4h x 16w) pixels, 256 threads, 4x4 regs/thread
__global__ __launch_bounds__(256) void conv3x3_relu(
    const float* __restrict__ x, const float* __restrict__ wgt,
    const float* __restrict__ bias) {
  const int wt = blockIdx.x;            // 0..3
  const int ht = blockIdx.y;            // 0..9
  const int kt = blockIdx.z;            // 0..7
  const int h0 = ht * 4, w0 = wt * 16;
  const int tid = threadIdx.x;
  const int ty  = tid >> 4;             // 0..15 (k groups of 4)
  const int txp = tid & 15;
  const int hh  = txp >> 2;             // 0..3
  const int wq  = txp & 3;              // 0..3 (w groups of 4)

  __shared__ float sW[64 * 72];         // [k][c*9+rs], conflict-free
  __shared__ float sX[8][6][20];        // [c][row][col], col0 = w0-1

  float acc[4][4];
#pragma unroll
  for (int i = 0; i < 4; ++i)
#pragma unroll
    for (int j = 0; j < 4; ++j) acc[i][j] = 0.f;

  const int k0g = kt * 64;

  for (int c0 = 0; c0 < C_IN; c0 += 8) {
    __syncthreads();
    // weights: 4608 floats, coalesced read, coalesced conflict-free store
#pragma unroll
    for (int l = 0; l < 18; ++l) {
      int idx = tid + l * 256;          // = k*72 + crs
      int k = idx / 72, crs = idx % 72;
      sW[idx] = wgt[(size_t)(k0g + k) * 4608 + (size_t)c0 * 9 + crs];
    }
    // input patch: 8c x 6rows x 20cols with zero padding
    for (int idx = tid; idx < 960; idx += 256) {
      int c = idx / 120, rem = idx % 120;
      int row = rem / 20, col = rem % 20;
      int gh = h0 - 1 + row, gw = w0 - 1 + col;
      float v = 0.f;
      if (gh >= 0 && gh < IH && gw >= 0 && gw < IW)
        v = x[(size_t)(c0 + c) * HWPIX + gh * IW + gw];
      sX[c][row][col] = v;
    }
    __syncthreads();

#pragma unroll 2
    for (int c = 0; c < 8; ++c) {
#pragma unroll
      for (int r = 0; r < 3; ++r) {
        const float* xp = &sX[c][hh + r][wq * 4];
        float4 xa = *(const float4*)xp;
        float2 xb = *(const float2*)(xp + 4);
        float xv[6] = {xa.x, xa.y, xa.z, xa.w, xb.x, xb.y};
#pragma unroll
        for (int s = 0; s < 3; ++s) {
          int widx = c * 9 + r * 3 + s;
          float a0 = sW[(ty * 4 + 0) * 72 + widx];
          float a1 = sW[(ty * 4 + 1) * 72 + widx];
          float a2 = sW[(ty * 4 + 2) * 72 + widx];
          float a3 = sW[(ty * 4 + 3) * 72 + widx];
#pragma unroll
          for (int j = 0; j < 4; ++j) {
            float xvv = xv[s + j];
            acc[0][j] = fmaf(a0, xvv, acc[0][j]);
            acc[1][j] = fmaf(a1, xvv, acc[1][j]);
            acc[2][j] = fmaf(a2, xvv, acc[2][j]);
            acc[3][j] = fmaf(a3, xvv, acc[3][j]);
          }
        }
      }
    }
  }

  // epilogue: bias + relu, store [p][k] as float4
  const int h = h0 + hh;
  if (h < IH) {
    float b0 = bias[k0g + ty * 4 + 0];
    float b1 = bias[k0g + ty * 4 + 1];
    float b2 = bias[k0g + ty * 4 + 2];
    float b3 = bias[k0g + ty * 4 + 3];
#pragma unroll
    for (int j = 0; j < 4; ++j) {
      int ww = w0 + wq * 4 + j;
      if (ww < IW) {
        int p = h * IW + ww;
        float4 o;
        o.x = fmaxf(acc[0][j] + b0, 0.f);
        o.y = fmaxf(acc[1][j] + b1, 0.f);
        o.z = fmaxf(acc[2][j] + b2, 0.f);
        o.w = fmaxf(acc[3][j] + b3, 0.f);
        *(float4*)(&g_h1T[(size_t)p * 512 + k0g + ty * 4]) = o;
      }
    }
  }
}

// ---------------- 1x1 heads + anchor decode + key build ----------------
__device__ __forceinline__ unsigned f2key(float f) {
  unsigned u = __float_as_uint(f);
  return (u & 0x80000000u) ? ~u : (u | 0x80000000u);
}

__global__ __launch_bounds__(256) void rpn_head(
    const float* __restrict__ loc_w, const float* __restrict__ loc_b,
    const float* __restrict__ score_w, const float* __restrict__ score_b) {
  const int p = blockIdx.x;             // 0..1899
  __shared__ float sh[512];
  __shared__ float sums[48];            // 36 loc + 9 fg
  const int tid = threadIdx.x;

  ((float2*)sh)[tid] = ((const float2*)(g_h1T + (size_t)p * 512))[tid];
  __syncthreads();

  const int wid = tid >> 5, lane = tid & 31;
  for (int o = wid; o < 45; o += 8) {
    const float* wrow;
    float bb;
    if (o < 36) { wrow = loc_w + (size_t)o * 512; bb = loc_b[o]; }
    else { int a = o - 36; wrow = score_w + (size_t)(2 * a + 1) * 512; bb = score_b[2 * a + 1]; }
    float s = 0.f;
#pragma unroll 4
    for (int c = lane; c < 512; c += 32) s = fmaf(wrow[c], sh[c], s);
#pragma unroll
    for (int off = 16; off; off >>= 1) s += __shfl_down_sync(0xffffffffu, s, off);
    if (lane == 0) sums[o] = s + bb;
  }
  __syncthreads();

  if (tid < 9) {
    const int a = tid;
    float dy = sums[a * 4 + 0], dx = sums[a * 4 + 1];
    float dh = sums[a * 4 + 2], dw = sums[a * 4 + 3];
    float fg = sums[36 + a];
    int h = p / IW, w = p % IW;
    float sy = (float)h * 16.f, sx = (float)w * 16.f;
    float ay0 = __fadd_rn(sy, c_ab[a][0]);
    float ax0 = __fadd_rn(sx, c_ab[a][1]);
    float ay1 = __fadd_rn(sy, c_ab[a][2]);
    float ax1 = __fadd_rn(sx, c_ab[a][3]);
    float ah = __fadd_rn(ay1, -ay0);
    float aw = __fadd_rn(ax1, -ax0);
    float acy = __fadd_rn(ay0, __fmul_rn(0.5f, ah));
    float acx = __fadd_rn(ax0, __fmul_rn(0.5f, aw));
    float cy = __fadd_rn(__fmul_rn(dy, ah), acy);
    float cx = __fadd_rn(__fmul_rn(dx, aw), acx);
    float bh = __fmul_rn(expf(dh), ah);
    float bw = __fmul_rn(expf(dw), aw);
    float y1 = fminf(fmaxf(__fadd_rn(cy, -__fmul_rn(0.5f, bh)), 0.f), 608.f);
    float x1 = fminf(fmaxf(__fadd_rn(cx, -__fmul_rn(0.5f, bw)), 0.f), 800.f);
    float y2 = fminf(fmaxf(__fadd_rn(cy,  __fmul_rn(0.5f, bh)), 0.f), 608.f);
    float x2 = fminf(fmaxf(__fadd_rn(cx,  __fmul_rn(0.5f, bw)), 0.f), 800.f);
    bool valid = (__fadd_rn(y2, -y1) >= 16.f) && (__fadd_rn(x2, -x1) >= 16.f);
    float sc = valid ? fg : -__int_as_float(0x7f800000);

    int i = p * 9 + a;
    g_box[i * 4 + 0] = y1; g_box[i * 4 + 1] = x1;
    g_box[i * 4 + 2] = y2; g_box[i * 4 + 3] = x2;
    g_keys[i] = ((unsigned long long)f2key(sc) << 32) |
                (unsigned long long)(~(unsigned)i);
  }
}

__global__ void pad_keys() {
  int i = NANCH + blockIdx.x * blockDim.x + threadIdx.x;
  if (i < NSORT) g_keys[i] = 0ull;
}

// ---------------- bitonic sort of 32768 keys (descending) ----------------
__global__ __launch_bounds__(1024) void bitonic_local_sort() {
  __shared__ unsigned long long s[4096];
  const int base = blockIdx.x * 4096;
  const int tid = threadIdx.x;
#pragma unroll
  for (int m = 0; m < 4; ++m) s[tid + m * 1024] = g_keys[base + tid + m * 1024];
  for (int k = 2; k <= 4096; k <<= 1) {
    for (int j = k >> 1; j > 0; j >>= 1) {
      __syncthreads();
#pragma unroll
      for (int m = 0; m < 2; ++m) {
        int t = tid + m * 1024;
        int i = ((t & ~(j - 1)) << 1) | (t & (j - 1));
        int ix = i | j;
        bool desc = (((base + i) & k) == 0);
        unsigned long long a = s[i], b = s[ix];
        if (desc ? (a < b) : (a > b)) { s[i] = b; s[ix] = a; }
      }
    }
  }
  __syncthreads();
#pragma unroll
  for (int m = 0; m < 4; ++m) g_keys[base + tid + m * 1024] = s[tid + m * 1024];
}

__global__ void bitonic_global(int k, int j) {
  int t = blockIdx.x * blockDim.x + threadIdx.x;   // 16384 threads
  int i = ((t & ~(j - 1)) << 1) | (t & (j - 1));
  int ix = i | j;
  bool desc = ((i & k) == 0);
  unsigned long long a = g_keys[i], b = g_keys[ix];
  if (desc ? (a < b) : (a > b)) { g_keys[i] = b; g_keys[ix] = a; }
}

__global__ __launch_bounds__(1024) void bitonic_local_tail(int k) {
  __shared__ unsigned long long s[4096];
  const int base = blockIdx.x * 4096;
  const int tid = threadIdx.x;
#pragma unroll
  for (int m = 0; m < 4; ++m) s[tid + m * 1024] = g_keys[base + tid + m * 1024];
  for (int j = 2048; j > 0; j >>= 1) {
    __syncthreads();
#pragma unroll
    for (int m = 0; m < 2; ++m) {
      int t = tid + m * 1024;
      int i = ((t & ~(j - 1)) << 1) | (t & (j - 1));
      int ix = i | j;
      bool desc = (((base + i) & k) == 0);
      unsigned long long a = s[i], b = s[ix];
      if (desc ? (a < b) : (a > b)) { s[i] = b; s[ix] = a; }
    }
  }
  __syncthreads();
#pragma unroll
  for (int m = 0; m < 4; ++m) g_keys[base + tid + m * 1024] = s[tid + m * 1024];
}

// ---------------- gather top boxes ----------------
__global__ void gather_top() {
  int t = blockIdx.x * 256 + threadIdx.x;
  if (t >= PRE_N) return;
  unsigned long long key = g_keys[t];
  unsigned idx = ~(unsigned)(key & 0xffffffffull);
  float4 b = make_float4(0.f, 0.f, 0.f, 0.f);
  if (idx < NANCH) b = ((const float4*)g_box)[idx];
  ((float4*)g_tb)[t] = b;
}

// ---------------- NMS suppression-mask matrix ----------------
__global__ __launch_bounds__(64) void nms_mask() {
  const int cb = blockIdx.x;      // col block
  const int rb = blockIdx.y;      // row block
  const int tid = threadIdx.x;
  __shared__ float4 colb[64];
  __shared__ float cola[64];
  int j0 = cb * 64;
  int jj = j0 + tid;
  float4 b = (jj < PRE_N) ? ((const float4*)g_tb)[jj] : make_float4(0.f,0.f,0.f,0.f);
  colb[tid] = b;
  cola[tid] = __fmul_rn(__fadd_rn(b.z, -b.x), __fadd_rn(b.w, -b.y));
  __syncthreads();
  int i = rb * 64 + tid;
  if (i >= PRE_N) return;
  float4 r = ((const float4*)g_tb)[i];
  float ra = __fmul_rn(__fadd_rn(r.z, -r.x), __fadd_rn(r.w, -r.y));
  unsigned long long bits = 0ull;
  int jmax = min(64, PRE_N - j0);
  for (int q = 0; q < jmax; ++q) {
    int j = j0 + q;
    if (j <= i) continue;
    float4 c = colb[q];
    float ty1 = fmaxf(r.x, c.x);
    float tx1 = fmaxf(r.y, c.y);
    float ty2 = fminf(r.z, c.z);
    float tx2 = fminf(r.w, c.w);
    float ihh = fmaxf(__fadd_rn(ty2, -ty1), 0.f);
    float iww = fmaxf(__fadd_rn(tx2, -tx1), 0.f);
    float inter = __fmul_rn(ihh, iww);
    float uni = fmaxf(__fadd_rn(__fadd_rn(ra, cola[q]), -inter), 1e-9f);
    float iou = __fdiv_rn(inter, uni);
    if (iou > 0.7f) bits |= (1ull << q);
  }
  g_mask[(size_t)i * MASKW + cb] = bits;
}

// ---------------- sequential NMS scan + output (early stop at 300) ------
__global__ __launch_bounds__(128) void nms_scan(float* __restrict__ out) {
  __shared__ unsigned long long remv[MASKW];
  __shared__ int s_keep, s_count, s_done;
  const int tid = threadIdx.x;
  if (tid < MASKW) remv[tid] = 0ull;
  if (tid == 0) { s_count = 0; s_done = 0; s_keep = 0; }
  for (int i = tid; i < POST_N * 4; i += blockDim.x) out[i] = 0.f;
  __syncthreads();

  for (int i = 0; i < PRE_N; ++i) {
    if (tid == 0) {
      unsigned hi = (unsigned)(g_keys[i] >> 32);
      bool valid = hi > 0x007FFFFFu;            // sortable(-inf) = 0x007FFFFF
      bool alive = valid && !((remv[i >> 6] >> (i & 63)) & 1ull);
      s_keep = alive ? 1 : 0;
      if (alive) {
        int rnk = s_count;
        s_count = rnk + 1;
        ((float4*)out)[rnk] = ((const float4*)g_tb)[i];
        if (s_count >= POST_N) s_done = 1;
      }
    }
    __syncthreads();
    if (s_done) break;
    if (s_keep && tid < MASKW) remv[tid] |= g_mask[(size_t)i * MASKW + tid];
    __syncthreads();
  }
}

// ---------------- launcher ----------------
extern "C" void kernel_launch(void* const* d_in, const int* in_sizes, int n_in,
                              void* d_out, int out_size) {
  const float* x        = (const float*)d_in[0];
  const float* conv1_w  = (const float*)d_in[1];
  const float* conv1_b  = (const float*)d_in[2];
  const float* loc_w    = (const float*)d_in[3];
  const float* loc_b    = (const float*)d_in[4];
  const float* score_w  = (const float*)d_in[5];
  const float* score_b  = (const float*)d_in[6];
  float* out = (float*)d_out;

  dim3 cgrid(4, 10, 8);
  conv3x3_relu<<<cgrid, 256>>>(x, conv1_w, conv1_b);

  rpn_head<<<HWPIX, 256>>>(loc_w, loc_b, score_w, score_b);
  pad_keys<<<(NSORT - NANCH + 255) / 256, 256>>>();

  bitonic_local_sort<<<8, 1024>>>();
  bitonic_global<<<64, 256>>>(8192, 4096);
  bitonic_local_tail<<<8, 1024>>>(8192);
  bitonic_global<<<64, 256>>>(16384, 8192);
  bitonic_global<<<64, 256>>>(16384, 4096);
  bitonic_local_tail<<<8, 1024>>>(16384);
  bitonic_global<<<64, 256>>>(32768, 16384);
  bitonic_global<<<64, 256>>>(32768, 8192);
  bitonic_global<<<64, 256>>>(32768, 4096);
  bitonic_local_tail<<<8, 1024>>>(32768);

  gather_top<<<(PRE_N + 255) / 256, 256>>>();
  nms_mask<<<dim3(MASKW, MASKW), 64>>>();
  nms_scan<<<1, 128>>>(out);
}

// round 2
// speedup vs baseline: 1.7387x; 1.7387x over previous
#include <cuda_runtime.h>

#define C_IN   512
#define K_OUT  512
#define IH     38
#define IW     50
#define HWPIX  1900
#define NANCH  17100
#define NSORT  32768
#define PRE_N  6000
#define POST_N 300
#define MASKW  94        // ceil(6000/64)

typedef unsigned long long ull;

// ---------------- device scratch (static, no allocation) ----------------
__device__ float g_h1T[HWPIX * K_OUT];                 // conv output, [pixel][k]
__device__ float g_box[NANCH * 4];                     // decoded clipped boxes
__device__ ull   g_keys[NSORT];                        // (score<<32)|~idx
__device__ float g_tb[PRE_N * 4];                      // top-6000 boxes (sorted)
__device__ ull   g_mask[(size_t)PRE_N * MASKW];        // zero-init; lower tri never written
__device__ ull   g_validw[96];                         // validity bits of top-6000

__constant__ float c_ab[9][4] = {
  {-37.254833f,  -82.50967f,   53.254833f,  98.50967f},
  {-82.50967f,  -173.01933f,   98.50967f,  189.01933f},
  {-173.01933f, -354.03867f,  189.01933f,  370.03867f},
  {-56.0f,       -56.0f,        72.0f,       72.0f},
  {-120.0f,     -120.0f,       136.0f,      136.0f},
  {-248.0f,     -248.0f,       264.0f,      264.0f},
  {-82.50967f,   -37.254833f,  98.50967f,   53.254833f},
  {-173.01933f,  -82.50967f,  189.01933f,   98.50967f},
  {-354.03867f, -173.01933f,  370.03867f,  189.01933f}};

// ---------------- f32x2 helpers ----------------
__device__ __forceinline__ ull dup2(float v) {
  ull r; asm("mov.b64 %0, {%1, %1};" : "=l"(r) : "f"(v)); return r;
}
__device__ __forceinline__ void fma2(ull& d, ull a, ull b) {
  asm("fma.rn.f32x2 %0, %1, %2, %0;" : "+l"(d) : "l"(a), "l"(b));
}
__device__ __forceinline__ float2 unpk(ull v) {
  float2 f; asm("mov.b64 {%0, %1}, %2;" : "=f"(f.x), "=f"(f.y) : "l"(v)); return f;
}

// ---------------- 3x3 conv + bias + relu -> g_h1T[p][k] ----------------
// tile: 64 output channels x (8h x 8w) pixels, 256 threads
// per thread: k-pair x2 (4 k) x 4 w-cols, packed f32x2 FMA
__global__ __launch_bounds__(256) void conv3x3_relu(
    const float* __restrict__ x, const float* __restrict__ wgt,
    const float* __restrict__ bias) {
  const int wt = blockIdx.x;            // 0..6
  const int ht = blockIdx.y;            // 0..4
  const int kt = blockIdx.z;            // 0..7
  const int h0 = ht * 8, w0 = wt * 8;
  const int tid = threadIdx.x;
  const int ty  = tid >> 4;             // 0..15 (k groups of 4)
  const int txp = tid & 15;
  const int hh  = txp >> 1;             // 0..7
  const int wq  = txp & 1;              // 0..1 (w groups of 4)

  __shared__ float sW[72 * 66];                     // [crs][k], stride 66
  __shared__ __align__(16) float sX[8][10][12];     // [c][row][col], col0 = w0-1

  ull a00 = 0, a01 = 0, a02 = 0, a03 = 0;   // (k0,k1) x j
  ull a10 = 0, a11 = 0, a12 = 0, a13 = 0;   // (k2,k3) x j

  const int k0g = kt * 64;

  for (int c0 = 0; c0 < C_IN; c0 += 8) {
    __syncthreads();
    // weights: 4608 floats, coalesced global read, 2-way-conflict smem store
#pragma unroll
    for (int l = 0; l < 18; ++l) {
      int idx = tid + l * 256;          // = k*72 + crs
      int k = idx / 72, crs = idx % 72;
      sW[crs * 66 + k] = wgt[(size_t)(k0g + k) * 4608 + (size_t)c0 * 9 + crs];
    }
    // input patch: 8c x 10rows x 10cols with zero padding
    for (int idx = tid; idx < 800; idx += 256) {
      int c = idx / 100, rem = idx % 100;
      int row = rem / 10, col = rem % 10;
      int gh = h0 - 1 + row, gw = w0 - 1 + col;
      float v = 0.f;
      if (gh >= 0 && gh < IH && gw >= 0 && gw < IW)
        v = x[(size_t)(c0 + c) * HWPIX + gh * IW + gw];
      sX[c][row][col] = v;
    }
    __syncthreads();

#pragma unroll 2
    for (int c = 0; c < 8; ++c) {
#pragma unroll
      for (int r = 0; r < 3; ++r) {
        const float* xp = &sX[c][hh + r][wq * 4];
        float4 xa = *(const float4*)xp;
        float2 xb = *(const float2*)(xp + 4);
        ull xd0 = dup2(xa.x), xd1 = dup2(xa.y), xd2 = dup2(xa.z);
        ull xd3 = dup2(xa.w), xd4 = dup2(xb.x), xd5 = dup2(xb.y);
        ull xd[6] = {xd0, xd1, xd2, xd3, xd4, xd5};
#pragma unroll
        for (int s = 0; s < 3; ++s) {
          int wi = (c * 9 + r * 3 + s) * 66 + ty * 4;
          ull w01 = *(const ull*)&sW[wi];
          ull w23 = *(const ull*)&sW[wi + 2];
          fma2(a00, w01, xd[s + 0]);
          fma2(a01, w01, xd[s + 1]);
          fma2(a02, w01, xd[s + 2]);
          fma2(a03, w01, xd[s + 3]);
          fma2(a10, w23, xd[s + 0]);
          fma2(a11, w23, xd[s + 1]);
          fma2(a12, w23, xd[s + 2]);
          fma2(a13, w23, xd[s + 3]);
        }
      }
    }
  }

  // epilogue: bias + relu, store [p][k0..k3] as float4
  const int h = h0 + hh;
  if (h < IH) {
    float b0 = bias[k0g + ty * 4 + 0];
    float b1 = bias[k0g + ty * 4 + 1];
    float b2 = bias[k0g + ty * 4 + 2];
    float b3 = bias[k0g + ty * 4 + 3];
    float2 p0[4] = {unpk(a00), unpk(a01), unpk(a02), unpk(a03)};
    float2 p1[4] = {unpk(a10), unpk(a11), unpk(a12), unpk(a13)};
#pragma unroll
    for (int j = 0; j < 4; ++j) {
      int ww = w0 + wq * 4 + j;
      if (ww < IW) {
        int p = h * IW + ww;
        float4 o;
        o.x = fmaxf(p0[j].x + b0, 0.f);
        o.y = fmaxf(p0[j].y + b1, 0.f);
        o.z = fmaxf(p1[j].x + b2, 0.f);
        o.w = fmaxf(p1[j].y + b3, 0.f);
        *(float4*)(&g_h1T[(size_t)p * 512 + k0g + ty * 4]) = o;
      }
    }
  }
}

// ---------------- 1x1 heads + anchor decode + key build (+pad) ----------
__device__ __forceinline__ unsigned f2key(float f) {
  unsigned u = __float_as_uint(f);
  return (u & 0x80000000u) ? ~u : (u | 0x80000000u);
}

__global__ __launch_bounds__(256) void rpn_head(
    const float* __restrict__ loc_w, const float* __restrict__ loc_b,
    const float* __restrict__ score_w, const float* __restrict__ score_b) {
  const int p = blockIdx.x;             // 0..1899 compute; >=1900 pad keys
  const int tid = threadIdx.x;
  if (p >= HWPIX) {
    int i = NANCH + (p - HWPIX) * 256 + tid;
    if (i < NSORT) g_keys[i] = 0ull;
    return;
  }
  __shared__ float sh[512];
  __shared__ float sums[48];            // 36 loc + 9 fg

  ((float2*)sh)[tid] = ((const float2*)(g_h1T + (size_t)p * 512))[tid];
  __syncthreads();

  const int wid = tid >> 5, lane = tid & 31;
  for (int o = wid; o < 45; o += 8) {
    const float* wrow;
    float bb;
    if (o < 36) { wrow = loc_w + (size_t)o * 512; bb = loc_b[o]; }
    else { int a = o - 36; wrow = score_w + (size_t)(2 * a + 1) * 512; bb = score_b[2 * a + 1]; }
    float s = 0.f;
#pragma unroll 4
    for (int c = lane; c < 512; c += 32) s = fmaf(wrow[c], sh[c], s);
#pragma unroll
    for (int off = 16; off; off >>= 1) s += __shfl_down_sync(0xffffffffu, s, off);
    if (lane == 0) sums[o] = s + bb;
  }
  __syncthreads();

  if (tid < 9) {
    const int a = tid;
    float dy = sums[a * 4 + 0], dx = sums[a * 4 + 1];
    float dh = sums[a * 4 + 2], dw = sums[a * 4 + 3];
    float fg = sums[36 + a];
    int h = p / IW, w = p % IW;
    float sy = (float)h * 16.f, sx = (float)w * 16.f;
    float ay0 = __fadd_rn(sy, c_ab[a][0]);
    float ax0 = __fadd_rn(sx, c_ab[a][1]);
    float ay1 = __fadd_rn(sy, c_ab[a][2]);
    float ax1 = __fadd_rn(sx, c_ab[a][3]);
    float ah = __fadd_rn(ay1, -ay0);
    float aw = __fadd_rn(ax1, -ax0);
    float acy = __fadd_rn(ay0, __fmul_rn(0.5f, ah));
    float acx = __fadd_rn(ax0, __fmul_rn(0.5f, aw));
    float cy = __fadd_rn(__fmul_rn(dy, ah), acy);
    float cx = __fadd_rn(__fmul_rn(dx, aw), acx);
    float bh = __fmul_rn(expf(dh), ah);
    float bw = __fmul_rn(expf(dw), aw);
    float y1 = fminf(fmaxf(__fadd_rn(cy, -__fmul_rn(0.5f, bh)), 0.f), 608.f);
    float x1 = fminf(fmaxf(__fadd_rn(cx, -__fmul_rn(0.5f, bw)), 0.f), 800.f);
    float y2 = fminf(fmaxf(__fadd_rn(cy,  __fmul_rn(0.5f, bh)), 0.f), 608.f);
    float x2 = fminf(fmaxf(__fadd_rn(cx,  __fmul_rn(0.5f, bw)), 0.f), 800.f);
    bool valid = (__fadd_rn(y2, -y1) >= 16.f) && (__fadd_rn(x2, -x1) >= 16.f);
    float sc = valid ? fg : -__int_as_float(0x7f800000);

    int i = p * 9 + a;
    g_box[i * 4 + 0] = y1; g_box[i * 4 + 1] = x1;
    g_box[i * 4 + 2] = y2; g_box[i * 4 + 3] = x2;
    g_keys[i] = ((ull)f2key(sc) << 32) | (ull)(~(unsigned)i);
  }
}

// ---------------- bitonic sort of 32768 keys (descending) ----------------
__global__ __launch_bounds__(1024) void bitonic_local_sort() {
  __shared__ ull s[4096];
  const int base = blockIdx.x * 4096;
  const int tid = threadIdx.x;
#pragma unroll
  for (int m = 0; m < 4; ++m) s[tid + m * 1024] = g_keys[base + tid + m * 1024];
  for (int k = 2; k <= 4096; k <<= 1) {
    for (int j = k >> 1; j > 0; j >>= 1) {
      __syncthreads();
#pragma unroll
      for (int m = 0; m < 2; ++m) {
        int t = tid + m * 1024;
        int i = ((t & ~(j - 1)) << 1) | (t & (j - 1));
        int ix = i | j;
        bool desc = (((base + i) & k) == 0);
        ull a = s[i], b = s[ix];
        if (desc ? (a < b) : (a > b)) { s[i] = b; s[ix] = a; }
      }
    }
  }
  __syncthreads();
#pragma unroll
  for (int m = 0; m < 4; ++m) g_keys[base + tid + m * 1024] = s[tid + m * 1024];
}

__global__ void bitonic_global(int k, int j) {
  int t = blockIdx.x * blockDim.x + threadIdx.x;   // 16384 threads
  int i = ((t & ~(j - 1)) << 1) | (t & (j - 1));
  int ix = i | j;
  bool desc = ((i & k) == 0);
  ull a = g_keys[i], b = g_keys[ix];
  if (desc ? (a < b) : (a > b)) { g_keys[i] = b; g_keys[ix] = a; }
}

__global__ __launch_bounds__(1024) void bitonic_local_tail(int k) {
  __shared__ ull s[4096];
  const int base = blockIdx.x * 4096;
  const int tid = threadIdx.x;
#pragma unroll
  for (int m = 0; m < 4; ++m) s[tid + m * 1024] = g_keys[base + tid + m * 1024];
  for (int j = 2048; j > 0; j >>= 1) {
    __syncthreads();
#pragma unroll
    for (int m = 0; m < 2; ++m) {
      int t = tid + m * 1024;
      int i = ((t & ~(j - 1)) << 1) | (t & (j - 1));
      int ix = i | j;
      bool desc = (((base + i) & k) == 0);
      ull a = s[i], b = s[ix];
      if (desc ? (a < b) : (a > b)) { s[i] = b; s[ix] = a; }
    }
  }
  __syncthreads();
#pragma unroll
  for (int m = 0; m < 4; ++m) g_keys[base + tid + m * 1024] = s[tid + m * 1024];
}

// ---------------- gather top boxes + validity ballot ----------------
__global__ void gather_top() {
  int t = blockIdx.x * 256 + threadIdx.x;         // 0..6143
  ull key = g_keys[t];
  bool valid = (t < PRE_N) && ((unsigned)(key >> 32) > 0x007FFFFFu);
  unsigned bal = __ballot_sync(0xffffffffu, valid);
  if ((threadIdx.x & 31) == 0) ((unsigned*)g_validw)[t >> 5] = bal;
  if (t < PRE_N) {
    unsigned idx = ~(unsigned)(key & 0xffffffffull);
    float4 b = make_float4(0.f, 0.f, 0.f, 0.f);
    if (idx < NANCH) b = ((const float4*)g_box)[idx];
    ((float4*)g_tb)[t] = b;
  }
}

// ---------------- NMS suppression-mask matrix (upper triangle) ----------
__global__ __launch_bounds__(64) void nms_mask() {
  const int cb = blockIdx.x;      // col block
  const int rb = blockIdx.y;      // row block
  if (cb < rb) return;            // lower triangle stays zero (never written)
  const int tid = threadIdx.x;
  __shared__ float4 colb[64];
  __shared__ float cola[64];
  int j0 = cb * 64;
  int jj = j0 + tid;
  float4 b = (jj < PRE_N) ? ((const float4*)g_tb)[jj] : make_float4(0.f,0.f,0.f,0.f);
  colb[tid] = b;
  cola[tid] = __fmul_rn(__fadd_rn(b.z, -b.x), __fadd_rn(b.w, -b.y));
  __syncthreads();
  int i = rb * 64 + tid;
  if (i >= PRE_N) return;
  float4 r = ((const float4*)g_tb)[i];
  float ra = __fmul_rn(__fadd_rn(r.z, -r.x), __fadd_rn(r.w, -r.y));
  ull bits = 0ull;
  int jmax = min(64, PRE_N - j0);
  for (int q = 0; q < jmax; ++q) {
    int j = j0 + q;
    if (j <= i) continue;
    float4 c = colb[q];
    float ty1 = fmaxf(r.x, c.x);
    float tx1 = fmaxf(r.y, c.y);
    float ty2 = fminf(r.z, c.z);
    float tx2 = fminf(r.w, c.w);
    float ihh = fmaxf(__fadd_rn(ty2, -ty1), 0.f);
    float iww = fmaxf(__fadd_rn(tx2, -tx1), 0.f);
    float inter = __fmul_rn(ihh, iww);
    float uni = fmaxf(__fadd_rn(__fadd_rn(ra, cola[q]), -inter), 1e-9f);
    float rhs = 0.7f * uni;
    bool sup;
    if (inter > rhs * 1.00001f)       sup = true;   // safely above threshold
    else if (inter < rhs * 0.99999f)  sup = false;  // safely below
    else sup = (__fdiv_rn(inter, uni) > 0.7f);      // exact (matches reference)
    if (sup) bits |= (1ull << q);
  }
  g_mask[(size_t)i * MASKW + cb] = bits;
}

// ---------- sequential NMS scan, warp-parallel word walk, stop@300 ------
__global__ __launch_bounds__(256) void nms_scan(float* __restrict__ out) {
  __shared__ ull remv[MASKW];
  __shared__ int keptIdx[POST_N];
  __shared__ int wordKept[64];
  __shared__ int s_nk, s_nwk;
  const int tid = threadIdx.x;
  if (tid < MASKW) remv[tid] = 0ull;
  if (tid == 0) { s_nk = 0; }
  for (int i = tid; i < POST_N * 4; i += 256) out[i] = 0.f;
  __syncthreads();

  for (int w = 0; w < MASKW; ++w) {
    if (tid < 32) {
      ull cur = remv[w];
      ull vw = g_validw[w];
      int base = w * 64;
      // prefetch the diagonal mask word for all 64 candidates of this word
      ull mA = ((vw >> tid) & 1ull) ? g_mask[(size_t)(base + tid) * MASKW + w] : 0ull;
      ull mB = ((vw >> (tid + 32)) & 1ull) ? g_mask[(size_t)(base + tid + 32) * MASKW + w] : 0ull;
      int nk = s_nk, nwk = 0;
      for (int q = 0; q < 64 && nk < POST_N; ++q) {
        ull mq = (q < 32) ? __shfl_sync(0xffffffffu, mA, q)
                          : __shfl_sync(0xffffffffu, mB, q - 32);
        if (((vw >> q) & 1ull) && !((cur >> q) & 1ull)) {
          if (tid == 0) { keptIdx[nk] = base + q; wordKept[nwk] = base + q; }
          cur |= mq;
          ++nk; ++nwk;
        }
      }
      if (tid == 0) { s_nk = nk; s_nwk = nwk; }
    }
    __syncthreads();
    // fold the full rows of this word's kept boxes into remv
    for (int r = 0; r < s_nwk; ++r) {
      int i = wordKept[r];
      if (tid < MASKW) remv[tid] |= g_mask[(size_t)i * MASKW + tid];
    }
    __syncthreads();
    if (s_nk >= POST_N) break;
  }

  __syncthreads();
  for (int r = tid; r < s_nk; r += 256)
    ((float4*)out)[r] = ((const float4*)g_tb)[keptIdx[r]];
}

// ---------------- launcher ----------------
extern "C" void kernel_launch(void* const* d_in, const int* in_sizes, int n_in,
                              void* d_out, int out_size) {
  const float* x        = (const float*)d_in[0];
  const float* conv1_w  = (const float*)d_in[1];
  const float* conv1_b  = (const float*)d_in[2];
  const float* loc_w    = (const float*)d_in[3];
  const float* loc_b    = (const float*)d_in[4];
  const float* score_w  = (const float*)d_in[5];
  const float* score_b  = (const float*)d_in[6];
  float* out = (float*)d_out;

  dim3 cgrid(7, 5, 8);
  conv3x3_relu<<<cgrid, 256>>>(x, conv1_w, conv1_b);

  rpn_head<<<HWPIX + 62, 256>>>(loc_w, loc_b, score_w, score_b);  // +62 pad blocks

  bitonic_local_sort<<<8, 1024>>>();
  bitonic_global<<<64, 256>>>(8192, 4096);
  bitonic_local_tail<<<8, 1024>>>(8192);
  bitonic_global<<<64, 256>>>(16384, 8192);
  bitonic_global<<<64, 256>>>(16384, 4096);
  bitonic_local_tail<<<8, 1024>>>(16384);
  bitonic_global<<<64, 256>>>(32768, 16384);
  bitonic_global<<<64, 256>>>(32768, 8192);
  bitonic_global<<<64, 256>>>(32768, 4096);
  bitonic_local_tail<<<8, 1024>>>(32768);

  gather_top<<<24, 256>>>();
  nms_mask<<<dim3(MASKW, MASKW), 64>>>();
  nms_scan<<<1, 256>>>(out);
}